// round 1
// baseline (speedup 1.0000x reference)
#include <cuda_runtime.h>
#include <math.h>

#define B_  4
#define S_  2048
#define H_  768
#define NH_ 12
#define D_  64
#define SCALE_ 0.125f   // 1/sqrt(64)

// Scratch Q/K/V, layout [b][h][s][d]
__device__ float g_Q[(size_t)B_ * NH_ * S_ * D_];
__device__ float g_K[(size_t)B_ * NH_ * S_ * D_];
__device__ float g_V[(size_t)B_ * NH_ * S_ * D_];

// ---------------------------------------------------------------------------
// Kernel 1: fused QKV projection.
// grid = (M/64, 36) where blockIdx.y = qkv*12 + h. Each block computes a
// 64x64 output tile of  out[m, d] = x_g[m, :] @ W_h[:, d] + bias_h[d]
// (Q rows additionally pre-scaled by 1/sqrt(D)).
// ---------------------------------------------------------------------------
__global__ __launch_bounds__(256) void qkv_proj(
    const float* __restrict__ e1, const float* __restrict__ e2,
    const float* __restrict__ e3,
    const float* __restrict__ Wq, const float* __restrict__ bq,
    const float* __restrict__ Wk, const float* __restrict__ bk,
    const float* __restrict__ Wv, const float* __restrict__ bv)
{
    const int h   = blockIdx.y % NH_;
    const int qkv = blockIdx.y / NH_;
    const int g   = h >> 2;

    const float* W    = (qkv == 0 ? Wq : (qkv == 1 ? Wk : Wv)) + (size_t)h * H_ * D_;
    const float* bias = (qkv == 0 ? bq : (qkv == 1 ? bk : bv)) + (size_t)h * D_;
    float*       out  = (qkv == 0 ? g_Q : (qkv == 1 ? g_K : g_V));
    const float* x    = (g == 0 ? e1 : (g == 1 ? e2 : e3));

    const int m0  = blockIdx.x * 64;
    const int tid = threadIdx.x;
    const int ty  = tid >> 4;      // 0..15
    const int tx  = tid & 15;      // 0..15

    __shared__ float As[64][33];   // [row][k], padded
    __shared__ float Ws[32][65];   // [k][d],  padded

    float acc[4][4] = {};

    for (int k0 = 0; k0 < H_; k0 += 32) {
        // Load A tile: 64 rows x 32 k  (512 float4)
        #pragma unroll
        for (int p = 0; p < 2; p++) {
            int f   = tid + p * 256;
            int row = f >> 3;
            int kq  = (f & 7) << 2;
            float4 v = *(const float4*)&x[(size_t)(m0 + row) * H_ + k0 + kq];
            As[row][kq + 0] = v.x; As[row][kq + 1] = v.y;
            As[row][kq + 2] = v.z; As[row][kq + 3] = v.w;
        }
        // Load W tile: 32 k x 64 d  (512 float4)
        #pragma unroll
        for (int p = 0; p < 2; p++) {
            int f   = tid + p * 256;
            int row = f >> 4;
            int dq  = (f & 15) << 2;
            float4 v = *(const float4*)&W[(size_t)(k0 + row) * D_ + dq];
            Ws[row][dq + 0] = v.x; Ws[row][dq + 1] = v.y;
            Ws[row][dq + 2] = v.z; Ws[row][dq + 3] = v.w;
        }
        __syncthreads();

        #pragma unroll
        for (int kk = 0; kk < 32; kk++) {
            float a[4], b[4];
            #pragma unroll
            for (int i = 0; i < 4; i++) a[i] = As[ty * 4 + i][kk];
            #pragma unroll
            for (int j = 0; j < 4; j++) b[j] = Ws[kk][tx * 4 + j];
            #pragma unroll
            for (int i = 0; i < 4; i++)
                #pragma unroll
                for (int j = 0; j < 4; j++)
                    acc[i][j] = fmaf(a[i], b[j], acc[i][j]);
        }
        __syncthreads();
    }

    const float scale = (qkv == 0) ? SCALE_ : 1.0f;
    float bj[4];
    #pragma unroll
    for (int j = 0; j < 4; j++) bj[j] = bias[tx * 4 + j];

    #pragma unroll
    for (int i = 0; i < 4; i++) {
        int m = m0 + ty * 4 + i;
        int bb = m >> 11;           // / S_
        int s  = m & (S_ - 1);
        size_t base = (((size_t)bb * NH_ + h) * S_ + s) * D_ + tx * 4;
        float4 o;
        o.x = (acc[i][0] + bj[0]) * scale;
        o.y = (acc[i][1] + bj[1]) * scale;
        o.z = (acc[i][2] + bj[2]) * scale;
        o.w = (acc[i][3] + bj[3]) * scale;
        *(float4*)&out[base] = o;
    }
}

// ---------------------------------------------------------------------------
// Kernel 2: flash attention per (b, h, q-tile of 64).
// grid = (S/64, B*NH). 256 threads, 4x4 register blocking.
// Smem pitch 65 everywhere -> conflict-free / <=2-way LDS.
// ---------------------------------------------------------------------------
__global__ __launch_bounds__(256) void attn(float* __restrict__ out)
{
    const int bh = blockIdx.y;
    const int bb = bh / NH_;
    const int h  = bh % NH_;
    const int q0 = blockIdx.x * 64;

    extern __shared__ float sm[];
    float (*Qs)[65] = (float(*)[65])sm;            // [q][d]
    float (*Ks)[65] = (float(*)[65])(sm + 64 * 65); // [k][d]
    float (*Vs)[65] = (float(*)[65])(sm + 2 * 64 * 65); // [k][d]
    float (*Ps)[65] = (float(*)[65])(sm + 3 * 64 * 65); // [k][q]  (transposed!)

    const size_t head_base = (((size_t)bb * NH_ + h) * S_) * D_;
    const float* Qb = g_Q + head_base;
    const float* Kb = g_K + head_base;
    const float* Vb = g_V + head_base;

    const int tid = threadIdx.x;
    const int ty  = tid >> 4;
    const int tx  = tid & 15;

    // Load Q tile (64x64)
    #pragma unroll
    for (int p = 0; p < 4; p++) {
        int f   = tid + p * 256;
        int row = f >> 4;
        int dq  = (f & 15) << 2;
        float4 v = *(const float4*)&Qb[(size_t)(q0 + row) * D_ + dq];
        Qs[row][dq + 0] = v.x; Qs[row][dq + 1] = v.y;
        Qs[row][dq + 2] = v.z; Qs[row][dq + 3] = v.w;
    }

    float m_i[4], l_i[4], acc[4][4] = {};
    #pragma unroll
    for (int i = 0; i < 4; i++) { m_i[i] = -INFINITY; l_i[i] = 0.0f; }

    for (int k0 = 0; k0 < S_; k0 += 64) {
        // Load K, V tiles
        #pragma unroll
        for (int p = 0; p < 4; p++) {
            int f   = tid + p * 256;
            int row = f >> 4;
            int dq  = (f & 15) << 2;
            float4 kv = *(const float4*)&Kb[(size_t)(k0 + row) * D_ + dq];
            Ks[row][dq + 0] = kv.x; Ks[row][dq + 1] = kv.y;
            Ks[row][dq + 2] = kv.z; Ks[row][dq + 3] = kv.w;
            float4 vv = *(const float4*)&Vb[(size_t)(k0 + row) * D_ + dq];
            Vs[row][dq + 0] = vv.x; Vs[row][dq + 1] = vv.y;
            Vs[row][dq + 2] = vv.z; Vs[row][dq + 3] = vv.w;
        }
        __syncthreads();

        // S = Q K^T  (Q pre-scaled by 1/sqrt(D))
        float s[4][4] = {};
        #pragma unroll
        for (int d = 0; d < 64; d++) {
            float a[4], b[4];
            #pragma unroll
            for (int i = 0; i < 4; i++) a[i] = Qs[ty * 4 + i][d];
            #pragma unroll
            for (int j = 0; j < 4; j++) b[j] = Ks[tx * 4 + j][d];
            #pragma unroll
            for (int i = 0; i < 4; i++)
                #pragma unroll
                for (int j = 0; j < 4; j++)
                    s[i][j] = fmaf(a[i], b[j], s[i][j]);
        }

        // Online softmax update (row reductions across the 16 tx lanes)
        #pragma unroll
        for (int i = 0; i < 4; i++) {
            float mx = fmaxf(fmaxf(s[i][0], s[i][1]), fmaxf(s[i][2], s[i][3]));
            #pragma unroll
            for (int off = 8; off >= 1; off >>= 1)
                mx = fmaxf(mx, __shfl_xor_sync(0xffffffffu, mx, off));
            float mnew  = fmaxf(m_i[i], mx);
            float alpha = __expf(m_i[i] - mnew);
            m_i[i] = mnew;

            float rs = 0.0f;
            #pragma unroll
            for (int j = 0; j < 4; j++) {
                float p = __expf(s[i][j] - mnew);
                s[i][j] = p;
                rs += p;
            }
            #pragma unroll
            for (int off = 8; off >= 1; off >>= 1)
                rs += __shfl_xor_sync(0xffffffffu, rs, off);
            l_i[i] = l_i[i] * alpha + rs;
            #pragma unroll
            for (int j = 0; j < 4; j++) acc[i][j] *= alpha;
        }

        // Stage P transposed: Ps[key][query]
        #pragma unroll
        for (int i = 0; i < 4; i++)
            #pragma unroll
            for (int j = 0; j < 4; j++)
                Ps[tx * 4 + j][ty * 4 + i] = s[i][j];
        __syncthreads();

        // acc += P V
        #pragma unroll
        for (int k = 0; k < 64; k++) {
            float a[4], b[4];
            #pragma unroll
            for (int i = 0; i < 4; i++) a[i] = Ps[k][ty * 4 + i];
            #pragma unroll
            for (int j = 0; j < 4; j++) b[j] = Vs[k][tx * 4 + j];
            #pragma unroll
            for (int i = 0; i < 4; i++)
                #pragma unroll
                for (int j = 0; j < 4; j++)
                    acc[i][j] = fmaf(a[i], b[j], acc[i][j]);
        }
        __syncthreads();   // protect Ks/Vs/Ps before next tile's loads
    }

    // Normalize and write: out[b, s, h*64 + d]
    #pragma unroll
    for (int i = 0; i < 4; i++) {
        float inv = 1.0f / l_i[i];
        int s_row = q0 + ty * 4 + i;
        size_t base = ((size_t)bb * S_ + s_row) * (NH_ * D_) + h * D_ + tx * 4;
        float4 o;
        o.x = acc[i][0] * inv;
        o.y = acc[i][1] * inv;
        o.z = acc[i][2] * inv;
        o.w = acc[i][3] * inv;
        *(float4*)&out[base] = o;
    }
}

// ---------------------------------------------------------------------------
extern "C" void kernel_launch(void* const* d_in, const int* in_sizes, int n_in,
                              void* d_out, int out_size)
{
    const float* e1 = (const float*)d_in[0];
    const float* e2 = (const float*)d_in[1];
    const float* e3 = (const float*)d_in[2];
    const float* Wq = (const float*)d_in[3];
    const float* bq = (const float*)d_in[4];
    const float* Wk = (const float*)d_in[5];
    const float* bk = (const float*)d_in[6];
    const float* Wv = (const float*)d_in[7];
    const float* bv = (const float*)d_in[8];
    float* out = (float*)d_out;

    // QKV projection: M tiles x (3 qkv * 12 heads)
    dim3 gproj((B_ * S_) / 64, 3 * NH_);
    qkv_proj<<<gproj, 256>>>(e1, e2, e3, Wq, bq, Wk, bk, Wv, bv);

    // Attention: q tiles x (B * NH)
    const int smem_bytes = 4 * 64 * 65 * sizeof(float);   // 66,560 B
    static bool attr_set = false;
    if (!attr_set) {
        cudaFuncSetAttribute(attn, cudaFuncAttributeMaxDynamicSharedMemorySize,
                             smem_bytes);
        attr_set = true;
    }
    dim3 gattn(S_ / 64, B_ * NH_);
    attn<<<gattn, 256, smem_bytes>>>(out);
}

// round 2
// speedup vs baseline: 3.3039x; 3.3039x over previous
#include <cuda_runtime.h>
#include <math.h>
#include <stdint.h>

#define B_  4
#define S_  2048
#define H_  768
#define NH_ 12
#define D_  64
#define SCALE_ 0.125f   // 1/sqrt(64)

// Scratch, layout [b][h][s][d]
__device__ float g_Q[(size_t)B_ * NH_ * S_ * D_];
__device__ float g_K[(size_t)B_ * NH_ * S_ * D_];
__device__ float g_V[(size_t)B_ * NH_ * S_ * D_];
// Transposed weights [qkv][h][d][H]  and V [b][h][d][s]
__device__ float g_WT[(size_t)3 * NH_ * D_ * H_];
__device__ float g_VT[(size_t)B_ * NH_ * D_ * S_];

// ---------------------------------------------------------------------------
__device__ __forceinline__ uint32_t f2tf32(float f) {
    uint32_t u;
    asm("cvt.rna.tf32.f32 %0, %1;" : "=r"(u) : "f"(f));
    return u;
}
__device__ __forceinline__ void mma_tf32(float c[4], uint32_t a0, uint32_t a1,
                                         uint32_t a2, uint32_t a3,
                                         uint32_t b0, uint32_t b1) {
    asm volatile(
        "mma.sync.aligned.m16n8k8.row.col.f32.tf32.tf32.f32 "
        "{%0,%1,%2,%3}, {%4,%5,%6,%7}, {%8,%9}, {%0,%1,%2,%3};"
        : "+f"(c[0]), "+f"(c[1]), "+f"(c[2]), "+f"(c[3])
        : "r"(a0), "r"(a1), "r"(a2), "r"(a3), "r"(b0), "r"(b1));
}

// ---------------------------------------------------------------------------
// Transpose W[h][H][D] -> g_WT[qkv][h][D][H]. grid (48, 36), 256 thr.
// ---------------------------------------------------------------------------
__global__ __launch_bounds__(256) void transpose_W(
    const float* __restrict__ Wq, const float* __restrict__ Wk,
    const float* __restrict__ Wv)
{
    const int qkv = blockIdx.y / NH_;
    const int h   = blockIdx.y % NH_;
    const float* W = (qkv == 0 ? Wq : (qkv == 1 ? Wk : Wv)) + (size_t)h * H_ * D_;
    float* WT = g_WT + (size_t)blockIdx.y * D_ * H_;

    const int kt = (blockIdx.x >> 1) * 32;   // k-tile (H dim)
    const int nt = (blockIdx.x & 1) * 32;    // n-tile (D dim)

    __shared__ float t[32][33];
    const int r  = threadIdx.x >> 3;          // 0..31
    const int c4 = (threadIdx.x & 7) * 4;     // 0,4,..28

    float4 v = *(const float4*)&W[(size_t)(kt + r) * D_ + nt + c4];
    t[r][c4 + 0] = v.x; t[r][c4 + 1] = v.y; t[r][c4 + 2] = v.z; t[r][c4 + 3] = v.w;
    __syncthreads();
    float4 o;
    o.x = t[c4 + 0][r]; o.y = t[c4 + 1][r]; o.z = t[c4 + 2][r]; o.w = t[c4 + 3][r];
    *(float4*)&WT[(size_t)(nt + r) * H_ + kt + c4] = o;
}

// ---------------------------------------------------------------------------
// Transpose g_V[bh][S][D] -> g_VT[bh][D][S]. grid (128, 48), 256 thr.
// ---------------------------------------------------------------------------
__global__ __launch_bounds__(256) void transpose_V()
{
    const int bh = blockIdx.y;
    const float* V = g_V + (size_t)bh * S_ * D_;
    float* VT = g_VT + (size_t)bh * D_ * S_;

    const int st = (blockIdx.x >> 1) * 32;   // seq tile
    const int dt = (blockIdx.x & 1) * 32;    // d tile

    __shared__ float t[32][33];
    const int r  = threadIdx.x >> 3;
    const int c4 = (threadIdx.x & 7) * 4;

    float4 v = *(const float4*)&V[(size_t)(st + r) * D_ + dt + c4];
    t[r][c4 + 0] = v.x; t[r][c4 + 1] = v.y; t[r][c4 + 2] = v.z; t[r][c4 + 3] = v.w;
    __syncthreads();
    float4 o;
    o.x = t[c4 + 0][r]; o.y = t[c4 + 1][r]; o.z = t[c4 + 2][r]; o.w = t[c4 + 3][r];
    *(float4*)&VT[(size_t)(dt + r) * S_ + st + c4] = o;
}

// ---------------------------------------------------------------------------
// QKV projection with tf32 mma. grid (64, 36), 256 thr (8 warps).
// Block tile: 128 rows x 64 cols. Warp tile: 32x32 (2 m-atoms x 4 n-atoms).
// ---------------------------------------------------------------------------
#define APITCH 36   // 36 % 32 == 4 -> conflict-free fragment loads
__global__ __launch_bounds__(256, 2) void qkv_proj_tc(
    const float* __restrict__ e1, const float* __restrict__ e2,
    const float* __restrict__ e3,
    const float* __restrict__ bq, const float* __restrict__ bk,
    const float* __restrict__ bv)
{
    const int h   = blockIdx.y % NH_;
    const int qkv = blockIdx.y / NH_;
    const int grp = h >> 2;

    const float* WT   = g_WT + (size_t)blockIdx.y * D_ * H_;    // [D][H]
    const float* bias = (qkv == 0 ? bq : (qkv == 1 ? bk : bv)) + (size_t)h * D_;
    float*       out  = (qkv == 0 ? g_Q : (qkv == 1 ? g_K : g_V));
    const float* x    = (grp == 0 ? e1 : (grp == 1 ? e2 : e3));

    const int m0  = blockIdx.x * 128;
    const int tid = threadIdx.x;
    const int w    = tid >> 5;
    const int lane = tid & 31;
    const int g    = lane >> 2;
    const int c    = lane & 3;
    const int m0w  = (w >> 1) * 32;   // warp row offset
    const int n0w  = (w & 1) * 32;    // warp col offset

    __shared__ float As[128 * APITCH];   // [row][k]
    __shared__ float Bs[64  * APITCH];   // [n=d][k]

    float Cf[2][4][4] = {};

    for (int kc = 0; kc < H_; kc += 32) {
        __syncthreads();
        // A tile 128x32 (1024 float4 -> 4/thread)
        #pragma unroll
        for (int p = 0; p < 4; p++) {
            int idx = tid + p * 256;
            int row = idx >> 3;
            int k4  = (idx & 7) * 4;
            float4 v = *(const float4*)&x[(size_t)(m0 + row) * H_ + kc + k4];
            float* d = &As[row * APITCH + k4];
            d[0] = __uint_as_float(f2tf32(v.x));
            d[1] = __uint_as_float(f2tf32(v.y));
            d[2] = __uint_as_float(f2tf32(v.z));
            d[3] = __uint_as_float(f2tf32(v.w));
        }
        // B tile 64x32 from WT (512 float4 -> 2/thread)
        #pragma unroll
        for (int p = 0; p < 2; p++) {
            int idx = tid + p * 256;
            int n   = idx >> 3;
            int k4  = (idx & 7) * 4;
            float4 v = *(const float4*)&WT[(size_t)n * H_ + kc + k4];
            float* d = &Bs[n * APITCH + k4];
            d[0] = __uint_as_float(f2tf32(v.x));
            d[1] = __uint_as_float(f2tf32(v.y));
            d[2] = __uint_as_float(f2tf32(v.z));
            d[3] = __uint_as_float(f2tf32(v.w));
        }
        __syncthreads();

        #pragma unroll
        for (int k0 = 0; k0 < 32; k0 += 8) {
            uint32_t a[2][4], b[4][2];
            #pragma unroll
            for (int ma = 0; ma < 2; ma++) {
                int r = m0w + ma * 16 + g;
                a[ma][0] = __float_as_uint(As[r * APITCH + k0 + c]);
                a[ma][1] = __float_as_uint(As[(r + 8) * APITCH + k0 + c]);
                a[ma][2] = __float_as_uint(As[r * APITCH + k0 + c + 4]);
                a[ma][3] = __float_as_uint(As[(r + 8) * APITCH + k0 + c + 4]);
            }
            #pragma unroll
            for (int na = 0; na < 4; na++) {
                int n = n0w + na * 8 + g;
                b[na][0] = __float_as_uint(Bs[n * APITCH + k0 + c]);
                b[na][1] = __float_as_uint(Bs[n * APITCH + k0 + c + 4]);
            }
            #pragma unroll
            for (int ma = 0; ma < 2; ma++)
                #pragma unroll
                for (int na = 0; na < 4; na++)
                    mma_tf32(Cf[ma][na], a[ma][0], a[ma][1], a[ma][2], a[ma][3],
                             b[na][0], b[na][1]);
        }
    }

    const float scale = (qkv == 0) ? SCALE_ : 1.0f;
    #pragma unroll
    for (int ma = 0; ma < 2; ma++) {
        #pragma unroll
        for (int na = 0; na < 4; na++) {
            int n = n0w + na * 8 + 2 * c;
            float b0 = bias[n], b1 = bias[n + 1];
            #pragma unroll
            for (int half = 0; half < 2; half++) {
                int m = m0 + m0w + ma * 16 + g + half * 8;
                int bb = m >> 11;
                int s  = m & (S_ - 1);
                size_t base = (((size_t)bb * NH_ + h) * S_ + s) * D_ + n;
                float2 o;
                o.x = (Cf[ma][na][half * 2 + 0] + b0) * scale;
                o.y = (Cf[ma][na][half * 2 + 1] + b1) * scale;
                *(float2*)&out[base] = o;
            }
        }
    }
}

// ---------------------------------------------------------------------------
// Flash attention with tf32 mma. grid (16, 48), 256 thr (8 warps).
// Block: 128 q-rows; k-tiles of 64. Warp: 16 q-rows x full 64-key width
// (softmax fully warp-local). P staged through smem, PV from g_VT.
// ---------------------------------------------------------------------------
#define PITCH 68    // 68 % 32 == 4 -> conflict-free fragment loads
__global__ __launch_bounds__(256, 2) void attn_tc(float* __restrict__ out)
{
    const int bh = blockIdx.y;
    const int bb = bh / NH_;
    const int h  = bh % NH_;
    const int q0 = blockIdx.x * 128;

    extern __shared__ float sm[];
    float* Qs = sm;                  // [128][PITCH]  (q, d)
    float* Ks = Qs + 128 * PITCH;    // [64][PITCH]   (key, d)
    float* Vt = Ks + 64 * PITCH;     // [64][PITCH]   (d, key)
    float* Ps = Vt + 64 * PITCH;     // [128][PITCH]  (q, key)

    const float* Qg  = g_Q  + (size_t)bh * S_ * D_;
    const float* Kg  = g_K  + (size_t)bh * S_ * D_;
    const float* VTg = g_VT + (size_t)bh * D_ * S_;

    const int tid  = threadIdx.x;
    const int w    = tid >> 5;
    const int lane = tid & 31;
    const int g    = lane >> 2;
    const int c    = lane & 3;
    const int m0   = w * 16;       // warp's q-row offset within block

    // Load Q tile 128x64 (2048 float4 -> 8/thread), tf32-rounded
    #pragma unroll
    for (int p = 0; p < 8; p++) {
        int idx = tid + p * 256;
        int row = idx >> 4;
        int c4  = (idx & 15) * 4;
        float4 v = *(const float4*)&Qg[(size_t)(q0 + row) * D_ + c4];
        float* d = &Qs[row * PITCH + c4];
        d[0] = __uint_as_float(f2tf32(v.x));
        d[1] = __uint_as_float(f2tf32(v.y));
        d[2] = __uint_as_float(f2tf32(v.z));
        d[3] = __uint_as_float(f2tf32(v.w));
    }

    float m_i[2] = {-INFINITY, -INFINITY};
    float l_i[2] = {0.0f, 0.0f};
    float O[8][4] = {};

    for (int kt = 0; kt < S_; kt += 64) {
        __syncthreads();   // previous tile's reads done before overwrite (covers Q load on iter 0)
        // K tile 64x64 (1024 float4 -> 4/thread)
        #pragma unroll
        for (int p = 0; p < 4; p++) {
            int idx = tid + p * 256;
            int row = idx >> 4;
            int c4  = (idx & 15) * 4;
            float4 v = *(const float4*)&Kg[(size_t)(kt + row) * D_ + c4];
            float* d = &Ks[row * PITCH + c4];
            d[0] = __uint_as_float(f2tf32(v.x));
            d[1] = __uint_as_float(f2tf32(v.y));
            d[2] = __uint_as_float(f2tf32(v.z));
            d[3] = __uint_as_float(f2tf32(v.w));
        }
        // V^T tile 64(d) x 64(key)
        #pragma unroll
        for (int p = 0; p < 4; p++) {
            int idx = tid + p * 256;
            int drow = idx >> 4;
            int k4   = (idx & 15) * 4;
            float4 v = *(const float4*)&VTg[(size_t)drow * S_ + kt + k4];
            float* d = &Vt[drow * PITCH + k4];
            d[0] = __uint_as_float(f2tf32(v.x));
            d[1] = __uint_as_float(f2tf32(v.y));
            d[2] = __uint_as_float(f2tf32(v.z));
            d[3] = __uint_as_float(f2tf32(v.w));
        }
        __syncthreads();

        // S = Q K^T : warp computes rows [m0, m0+16) x 64 keys
        float Sf[8][4] = {};
        #pragma unroll
        for (int k0 = 0; k0 < 64; k0 += 8) {
            uint32_t a0 = __float_as_uint(Qs[(m0 + g) * PITCH + k0 + c]);
            uint32_t a1 = __float_as_uint(Qs[(m0 + g + 8) * PITCH + k0 + c]);
            uint32_t a2 = __float_as_uint(Qs[(m0 + g) * PITCH + k0 + c + 4]);
            uint32_t a3 = __float_as_uint(Qs[(m0 + g + 8) * PITCH + k0 + c + 4]);
            #pragma unroll
            for (int na = 0; na < 8; na++) {
                uint32_t b0 = __float_as_uint(Ks[(na * 8 + g) * PITCH + k0 + c]);
                uint32_t b1 = __float_as_uint(Ks[(na * 8 + g) * PITCH + k0 + c + 4]);
                mma_tf32(Sf[na], a0, a1, a2, a3, b0, b1);
            }
        }

        // Online softmax. Thread owns rows (m0+g) [regs 0,1] and (m0+g+8) [2,3].
        #pragma unroll
        for (int half = 0; half < 2; half++) {
            float mx = -INFINITY;
            #pragma unroll
            for (int na = 0; na < 8; na++)
                mx = fmaxf(mx, fmaxf(Sf[na][half * 2], Sf[na][half * 2 + 1]));
            mx = fmaxf(mx, __shfl_xor_sync(0xffffffffu, mx, 1));
            mx = fmaxf(mx, __shfl_xor_sync(0xffffffffu, mx, 2));
            float mnew  = fmaxf(m_i[half], mx);
            float alpha = __expf(m_i[half] - mnew);
            m_i[half] = mnew;
            float rs = 0.0f;
            #pragma unroll
            for (int na = 0; na < 8; na++) {
                float p0 = __expf(Sf[na][half * 2]     - mnew);
                float p1 = __expf(Sf[na][half * 2 + 1] - mnew);
                Sf[na][half * 2]     = p0;
                Sf[na][half * 2 + 1] = p1;
                rs += p0 + p1;
            }
            rs += __shfl_xor_sync(0xffffffffu, rs, 1);
            rs += __shfl_xor_sync(0xffffffffu, rs, 2);
            l_i[half] = l_i[half] * alpha + rs;
            #pragma unroll
            for (int na = 0; na < 8; na++) {
                O[na][half * 2]     *= alpha;
                O[na][half * 2 + 1] *= alpha;
            }
        }

        // Stage P (tf32-rounded) to warp-private smem rows
        #pragma unroll
        for (int na = 0; na < 8; na++) {
            float2 p0, p1;
            p0.x = __uint_as_float(f2tf32(Sf[na][0]));
            p0.y = __uint_as_float(f2tf32(Sf[na][1]));
            p1.x = __uint_as_float(f2tf32(Sf[na][2]));
            p1.y = __uint_as_float(f2tf32(Sf[na][3]));
            *(float2*)&Ps[(m0 + g) * PITCH + na * 8 + 2 * c]     = p0;
            *(float2*)&Ps[(m0 + g + 8) * PITCH + na * 8 + 2 * c] = p1;
        }
        __syncwarp();

        // O += P V : A = Ps (warp rows, k=keys), B = Vt (n=d, k=keys)
        #pragma unroll
        for (int k0 = 0; k0 < 64; k0 += 8) {
            uint32_t a0 = __float_as_uint(Ps[(m0 + g) * PITCH + k0 + c]);
            uint32_t a1 = __float_as_uint(Ps[(m0 + g + 8) * PITCH + k0 + c]);
            uint32_t a2 = __float_as_uint(Ps[(m0 + g) * PITCH + k0 + c + 4]);
            uint32_t a3 = __float_as_uint(Ps[(m0 + g + 8) * PITCH + k0 + c + 4]);
            #pragma unroll
            for (int na = 0; na < 8; na++) {
                uint32_t b0 = __float_as_uint(Vt[(na * 8 + g) * PITCH + k0 + c]);
                uint32_t b1 = __float_as_uint(Vt[(na * 8 + g) * PITCH + k0 + c + 4]);
                mma_tf32(O[na], a0, a1, a2, a3, b0, b1);
            }
        }
    }

    // Epilogue: normalize and write out[b][s][h*64+d]
    float inv0 = 1.0f / l_i[0];
    float inv1 = 1.0f / l_i[1];
    #pragma unroll
    for (int na = 0; na < 8; na++) {
        int d0 = na * 8 + 2 * c;
        int r0 = q0 + m0 + g;
        size_t base0 = ((size_t)bb * S_ + r0) * (NH_ * D_) + h * D_ + d0;
        float2 o0; o0.x = O[na][0] * inv0; o0.y = O[na][1] * inv0;
        *(float2*)&out[base0] = o0;
        size_t base1 = ((size_t)bb * S_ + r0 + 8) * (NH_ * D_) + h * D_ + d0;
        float2 o1; o1.x = O[na][2] * inv1; o1.y = O[na][3] * inv1;
        *(float2*)&out[base1] = o1;
    }
}

// ---------------------------------------------------------------------------
extern "C" void kernel_launch(void* const* d_in, const int* in_sizes, int n_in,
                              void* d_out, int out_size)
{
    const float* e1 = (const float*)d_in[0];
    const float* e2 = (const float*)d_in[1];
    const float* e3 = (const float*)d_in[2];
    const float* Wq = (const float*)d_in[3];
    const float* bq = (const float*)d_in[4];
    const float* Wk = (const float*)d_in[5];
    const float* bk = (const float*)d_in[6];
    const float* Wv = (const float*)d_in[7];
    const float* bv = (const float*)d_in[8];
    float* out = (float*)d_out;

    const int attn_smem = 384 * PITCH * sizeof(float);   // 104448 B
    static bool attr_set = false;
    if (!attr_set) {
        cudaFuncSetAttribute(attn_tc, cudaFuncAttributeMaxDynamicSharedMemorySize,
                             attn_smem);
        attr_set = true;
    }

    transpose_W<<<dim3(48, 36), 256>>>(Wq, Wk, Wv);
    qkv_proj_tc<<<dim3((B_ * S_) / 128, 36), 256>>>(e1, e2, e3, bq, bk, bv);
    transpose_V<<<dim3(128, B_ * NH_), 256>>>();
    attn_tc<<<dim3(S_ / 128, B_ * NH_), 256, attn_smem>>>(out);
}